// round 7
// baseline (speedup 1.0000x reference)
#include <cuda_runtime.h>

#define CH           30
#define CELLS        64
#define THREADS      128
#define STAGES       3
#define GRID         608                  // 152 SMs x 4 resident blocks (persistent)
#define TILE_FLOATS  (CELLS * CH)         // 1920 floats = 7680 B per array per tile
#define TILE_V4      (TILE_FLOATS / 4)    // 480 float4 per array per tile
#define STAGE_FLOATS (2 * TILE_FLOATS)    // pred + target per stage = 15360 B

// Deterministic scratch (no device-side allocation).
__device__ float        g_partials[GRID];
__device__ unsigned int g_count = 0;      // self-resetting mod GRID across graph replays

__device__ __forceinline__ void cp16(void* smem_dst, const void* gmem_src) {
    unsigned int d = (unsigned int)__cvta_generic_to_shared(smem_dst);
    asm volatile("cp.async.cg.shared.global [%0], [%1], 16;\n" :: "r"(d), "l"(gmem_src));
}
__device__ __forceinline__ void cp_commit() { asm volatile("cp.async.commit_group;\n" ::: "memory"); }
__device__ __forceinline__ void cp_wait1()  { asm volatile("cp.async.wait_group 1;\n" ::: "memory"); }

__device__ __forceinline__ float warp_reduce(float v) {
#pragma unroll
    for (int o = 16; o > 0; o >>= 1) v += __shfl_xor_sync(0xffffffffu, v, o);
    return v;
}

__global__ void __launch_bounds__(THREADS)
yolo_fused(const float* __restrict__ pred, const float* __restrict__ targ,
           int n_tiles, float* __restrict__ out, int out_size) {
    extern __shared__ float sm[];   // STAGES x (pred tile + target tile) = 46080 B
    const int tid = threadIdx.x;
    const int bid = blockIdx.x;

    // CONTIGUOUS chunk per block (TLB-friendly): block b owns tiles
    // [start, start+iters). Consecutive tiles are adjacent in memory, so each
    // CTA streams sequentially through ~320 KB regions of pred/targ and its
    // 2MB-page working set is 1 page per array (vs. a fresh page per tile
    // under grid-striding -> PTW storm with 385MB footprint > 256MB TLB reach).
    const int q = n_tiles / GRID;              // 41
    const int r = n_tiles % GRID;              // 160
    const int iters = q + (bid < r);
    const int start = bid * q + min(bid, r);

    auto load_stage = [&](int i, int stage) {
        if (i < iters) {
            const long long tile = start + i;
            const float4* p4 = reinterpret_cast<const float4*>(pred + tile * TILE_FLOATS);
            const float4* t4 = reinterpret_cast<const float4*>(targ + tile * TILE_FLOATS);
            float4* sp = reinterpret_cast<float4*>(sm + stage * STAGE_FLOATS);
            float4* st = reinterpret_cast<float4*>(sm + stage * STAGE_FLOATS + TILE_FLOATS);
#pragma unroll
            for (int k = tid; k < TILE_V4; k += THREADS) {
                cp16(sp + k, p4 + k);
                cp16(st + k, t4 + k);
            }
        }
        cp_commit();  // commit (possibly empty) group to keep wait arithmetic uniform
    };

    // Prefetch 2 tiles ahead
    load_stage(0, 0);
    load_stage(1, 1);

    // Thread-pair split: half 0 handles boxes/IoU/conf, half 1 handles class term.
    const int half = tid >> 6;        // 0 or 1
    const int cell = tid & 63;        // cell within tile

    float acc = 0.f;
    int stage = 0;
    for (int i = 0; i < iters; i++) {
        cp_wait1();          // <=1 group pending -> stage i's copy complete
        __syncthreads();     // block-wide visibility of stage i.
                             // NOTE: also orders last reads of stage (i-1)%3 before
                             // load_stage(i+2) below overwrites it -> no 2nd barrier.

        const float* p = sm + stage * STAGE_FLOATS + cell * CH;
        const float* t = sm + stage * STAGE_FLOATS + TILE_FLOATS + cell * CH;
        const float t4v = t[4];

        if (half == 0) {
            // IoU of both pred boxes vs the target box
            const float tx0 = t[0], ty0 = t[1], tx1 = t[2], ty1 = t[3];
            const float area2 = (tx1 - tx0) * (ty1 - ty0);
            float iou0, iou1;
#pragma unroll
            for (int b = 0; b < 2; b++) {
                const int o = b * 5;
                const float x0 = p[o + 0], y0 = p[o + 1];
                const float x1 = p[o + 2], y1 = p[o + 3];
                float w = fminf(x1, tx1) - fmaxf(x0, tx0);
                float h = fminf(y1, ty1) - fmaxf(y0, ty0);
                w = fmaxf(w, 0.f);
                h = fmaxf(h, 0.f);
                const float inter = w * h;
                const float area1 = (x1 - x0) * (y1 - y0);
                const float iou = inter / (area1 + area2 - inter);
                if (b == 0) iou0 = iou; else iou1 = iou;
            }
            // argmax with first-index tiebreak: box 0 wins unless iou1 strictly greater
            const int o = (iou1 > iou0) ? 5 : 0;

            const float dx = p[o + 0] - t[o + 0];
            const float dy = p[o + 1] - t[o + 1];
            const float l1 = dx * dx + dy * dy;

            const float dw = sqrtf(p[o + 2]) - sqrtf(t[o + 2]);
            const float dh = sqrtf(p[o + 3]) - sqrtf(t[o + 3]);
            const float l2 = dw * dw + dh * dh;

            const float dc = p[o + 4] - t[o + 4];
            const float conf = dc * dc;

            if (t4v > 0.f)       acc += 5.0f * (l1 + l2) + conf;  // obj
            else if (t4v == 0.f) acc += 0.5f * conf;              // noobj
        } else {
            // class-probability term (only contributes when obj)
            if (t4v > 0.f) {
                float s5 = 0.f;
#pragma unroll
                for (int c = 10; c < 30; c++) {
                    const float d = p[c] - t[c];
                    s5 += d * d;
                }
                acc += s5;
            }
        }

        // Prefetch tile i+2 into the stage freed at iteration i-1 (safe: see barrier note)
        const int next = (stage + 2 >= STAGES) ? stage + 2 - STAGES : stage + 2;
        load_stage(i + 2, next);
        stage = (stage + 1 == STAGES) ? 0 : stage + 1;
    }

    // ---- block reduction ---------------------------------------------------
    __syncthreads();              // smem free for reuse
    float w = warp_reduce(acc);
    if ((tid & 31) == 0) sm[tid >> 5] = w;
    __syncthreads();
    __shared__ bool s_last;
    if (tid == 0) {
        float v = 0.f;
#pragma unroll
        for (int j = 0; j < THREADS / 32; j++) v += sm[j];
        g_partials[bid] = v;
        __threadfence();
        unsigned int old = atomicAdd(&g_count, 1u);
        s_last = (((old + 1u) % GRID) == 0u);   // wraps -> valid on every graph replay
    }
    __syncthreads();

    // ---- last block finishes the reduction (deterministic order) -----------
    if (s_last) {
        __threadfence();
        float v = 0.f;
        for (int k = tid; k < GRID; k += THREADS) v += g_partials[k];
        v = warp_reduce(v);
        if ((tid & 31) == 0) sm[tid >> 5] = v;
        __syncthreads();
        if (tid == 0) {
            float tot = 0.f;
#pragma unroll
            for (int j = 0; j < THREADS / 32; j++) tot += sm[j];
            out[0] = tot;
        }
        // d_out is poisoned to 0xAA; clear any extra elements
        for (int k = tid + 1; k < out_size; k += THREADS) out[k] = 0.f;
    }
}

extern "C" void kernel_launch(void* const* d_in, const int* in_sizes, int n_in,
                              void* d_out, int out_size) {
    const float* pred = (const float*)d_in[0];
    const float* targ = (const float*)d_in[1];
    float* out = (float*)d_out;
    const int n_cells = in_sizes[0] / CH;     // 1,605,632
    const int n_tiles = n_cells / CELLS;      // 25,088

    const size_t smem = (size_t)STAGES * STAGE_FLOATS * sizeof(float);  // 46080 B
    cudaFuncSetAttribute(yolo_fused, cudaFuncAttributeMaxDynamicSharedMemorySize, (int)smem);

    yolo_fused<<<GRID, THREADS, smem>>>(pred, targ, n_tiles, out, out_size);
}

// round 8
// speedup vs baseline: 1.1256x; 1.1256x over previous
#include <cuda_runtime.h>
#include <cstdint>

#define CH           30
#define CELLS        128
#define THREADS      128
#define STAGES       3
#define GRID         304                   // 152 SMs x 2 resident blocks (persistent)
#define TILE_FLOATS  (CELLS * CH)          // 3840 floats = 15360 B per array per tile
#define TILE_BYTES   (TILE_FLOATS * 4)     // 15360
#define STAGE_FLOATS (2 * TILE_FLOATS)     // pred + target per stage
#define STAGE_BYTES  (2 * TILE_BYTES)      // 30720
#define DATA_OFF     32                    // floats; first 128 B hold mbarriers

// Deterministic scratch (no device-side allocation).
__device__ float        g_partials[GRID];
__device__ unsigned int g_count = 0;       // self-resetting mod GRID across graph replays

__device__ __forceinline__ uint32_t smem_u32(const void* p) {
    return (uint32_t)__cvta_generic_to_shared(p);
}

__device__ __forceinline__ void mbar_init(uint32_t mbar, uint32_t count) {
    asm volatile("mbarrier.init.shared.b64 [%0], %1;" :: "r"(mbar), "r"(count) : "memory");
}
__device__ __forceinline__ void mbar_expect_tx(uint32_t mbar, uint32_t bytes) {
    asm volatile("mbarrier.arrive.expect_tx.shared.b64 _, [%0], %1;"
                 :: "r"(mbar), "r"(bytes) : "memory");
}
__device__ __forceinline__ void tma_bulk_1d(uint32_t dst_smem, const void* src, uint32_t bytes,
                                            uint32_t mbar) {
    asm volatile("cp.async.bulk.shared::cta.global.mbarrier::complete_tx::bytes "
                 "[%0], [%1], %2, [%3];"
                 :: "r"(dst_smem), "l"(src), "r"(bytes), "r"(mbar) : "memory");
}
__device__ __forceinline__ void mbar_wait(uint32_t mbar, uint32_t parity) {
    uint32_t done;
    asm volatile("{\n\t.reg .pred p;\n\t"
                 "mbarrier.try_wait.parity.acquire.cta.shared::cta.b64 p, [%1], %2;\n\t"
                 "selp.b32 %0, 1, 0, p;\n\t}"
                 : "=r"(done) : "r"(mbar), "r"(parity) : "memory");
    if (!done) {
        asm volatile("{\n\t.reg .pred P1;\n\t"
                     "WAIT_LOOP_%=:\n\t"
                     "mbarrier.try_wait.parity.acquire.cta.shared::cta.b64 P1, [%0], %1, 0x989680;\n\t"
                     "@P1 bra.uni WAIT_DONE_%=;\n\t"
                     "bra.uni WAIT_LOOP_%=;\n\t"
                     "WAIT_DONE_%=:\n\t}"
                     :: "r"(mbar), "r"(parity) : "memory");
    }
}

__device__ __forceinline__ float warp_reduce(float v) {
#pragma unroll
    for (int o = 16; o > 0; o >>= 1) v += __shfl_xor_sync(0xffffffffu, v, o);
    return v;
}

__global__ void __launch_bounds__(THREADS)
yolo_fused(const float* __restrict__ pred, const float* __restrict__ targ,
           int n_tiles, float* __restrict__ out, int out_size) {
    extern __shared__ float sm[];   // [128B mbarriers][STAGES x 30720B data] = 92288 B
    const int tid = threadIdx.x;
    const int bid = blockIdx.x;

    const uint32_t smbase = smem_u32(sm);
    // Grid-strided tiles (measured better than contiguous): tile = bid + i*GRID
    const int iters = (n_tiles - bid + GRID - 1) / GRID;

    if (tid == 0) {
#pragma unroll
        for (int s = 0; s < STAGES; s++) mbar_init(smbase + s * 8, 1);
    }
    __syncthreads();   // barriers visible before any TMA issue / wait

    auto issue = [&](int i, int stage) {   // called by tid 0 only
        if (i < iters) {
            const long long tile = bid + (long long)i * GRID;
            const uint32_t mbar = smbase + stage * 8;
            const uint32_t dst  = smbase + (DATA_OFF + stage * STAGE_FLOATS) * 4;
            mbar_expect_tx(mbar, STAGE_BYTES);
            tma_bulk_1d(dst,              pred + tile * TILE_FLOATS, TILE_BYTES, mbar);
            tma_bulk_1d(dst + TILE_BYTES, targ + tile * TILE_FLOATS, TILE_BYTES, mbar);
        }
    };

    if (tid == 0) { issue(0, 0); issue(1, 1); }

    float acc = 0.f;
    for (int i = 0; i < iters; i++) {
        const int stage = (i % STAGES);
        const uint32_t parity = (uint32_t)((i / STAGES) & 1);
        mbar_wait(smbase + stage * 8, parity);   // acquire: TMA data visible

        const float* p = sm + DATA_OFF + stage * STAGE_FLOATS + tid * CH;
        const float* t = p + TILE_FLOATS;
        const float t4v = t[4];

        // IoU of both pred boxes vs the target box
        const float tx0 = t[0], ty0 = t[1], tx1 = t[2], ty1 = t[3];
        const float area2 = (tx1 - tx0) * (ty1 - ty0);
        float iou0, iou1;
#pragma unroll
        for (int b = 0; b < 2; b++) {
            const int o = b * 5;
            const float x0 = p[o + 0], y0 = p[o + 1];
            const float x1 = p[o + 2], y1 = p[o + 3];
            float w = fminf(x1, tx1) - fmaxf(x0, tx0);
            float h = fminf(y1, ty1) - fmaxf(y0, ty0);
            w = fmaxf(w, 0.f);
            h = fmaxf(h, 0.f);
            const float inter = w * h;
            const float area1 = (x1 - x0) * (y1 - y0);
            const float iou = inter / (area1 + area2 - inter);
            if (b == 0) iou0 = iou; else iou1 = iou;
        }
        // argmax with first-index tiebreak: box 0 wins unless iou1 strictly greater
        const int o = (iou1 > iou0) ? 5 : 0;

        if (t4v > 0.f) {
            const float dx = p[o + 0] - t[o + 0];
            const float dy = p[o + 1] - t[o + 1];
            const float l1 = dx * dx + dy * dy;

            const float dw = sqrtf(p[o + 2]) - sqrtf(t[o + 2]);
            const float dh = sqrtf(p[o + 3]) - sqrtf(t[o + 3]);
            const float l2 = dw * dw + dh * dh;

            const float dc = p[o + 4] - t[o + 4];

            float s5 = 0.f;
#pragma unroll
            for (int c = 10; c < 30; c++) {
                const float d = p[c] - t[c];
                s5 += d * d;
            }
            acc += 5.0f * (l1 + l2) + dc * dc + s5;      // obj
        } else if (t4v == 0.f) {
            const float dc = p[o + 4] - t[o + 4];
            acc += 0.5f * (dc * dc);                     // noobj
        }

        // All threads done reading stage (i)%3; stage (i+2)%3 was last read at
        // iteration i-1, and this barrier also orders those reads -> safe to refill.
        __syncthreads();
        if (tid == 0) issue(i + 2, (i + 2) % STAGES);
    }

    // ---- block reduction (reuse data area of smem) --------------------------
    __syncthreads();
    float w = warp_reduce(acc);
    float* red = sm + DATA_OFF;
    if ((tid & 31) == 0) red[tid >> 5] = w;
    __syncthreads();
    __shared__ bool s_last;
    if (tid == 0) {
        float v = 0.f;
#pragma unroll
        for (int j = 0; j < THREADS / 32; j++) v += red[j];
        g_partials[bid] = v;
        __threadfence();
        unsigned int old = atomicAdd(&g_count, 1u);
        s_last = (((old + 1u) % GRID) == 0u);   // wraps -> valid on every graph replay
    }
    __syncthreads();

    // ---- last block finishes the reduction (deterministic order) ------------
    if (s_last) {
        __threadfence();
        float v = 0.f;
        for (int k = tid; k < GRID; k += THREADS) v += g_partials[k];
        v = warp_reduce(v);
        if ((tid & 31) == 0) red[tid >> 5] = v;
        __syncthreads();
        if (tid == 0) {
            float tot = 0.f;
#pragma unroll
            for (int j = 0; j < THREADS / 32; j++) tot += red[j];
            out[0] = tot;
        }
        // d_out is poisoned to 0xAA; clear any extra elements
        for (int k = tid + 1; k < out_size; k += THREADS) out[k] = 0.f;
    }
}

extern "C" void kernel_launch(void* const* d_in, const int* in_sizes, int n_in,
                              void* d_out, int out_size) {
    const float* pred = (const float*)d_in[0];
    const float* targ = (const float*)d_in[1];
    float* out = (float*)d_out;
    const int n_cells = in_sizes[0] / CH;     // 1,605,632
    const int n_tiles = n_cells / CELLS;      // 12,544

    const size_t smem = (size_t)(DATA_OFF + STAGES * STAGE_FLOATS) * sizeof(float); // 92288 B
    cudaFuncSetAttribute(yolo_fused, cudaFuncAttributeMaxDynamicSharedMemorySize, (int)smem);

    yolo_fused<<<GRID, THREADS, smem>>>(pred, targ, n_tiles, out, out_size);
}